// round 1
// baseline (speedup 1.0000x reference)
#include <cuda_runtime.h>

#define BB   64
#define CHN  3
#define HWP  (224*224)        // 50176
#define KBIG (CHN*HWP)        // 150528
#define EMB  512
#define HIST 300
#define CONC 812              // 512 + 300
#define HID  400

#define KT   64
#define KTP  68               // padded smem row stride (floats), 16B aligned
#define NTILES_K 2352         // KBIG / KT
#define KSPLIT   37
#define TPB_K    64           // k-tiles per block (ceil(2352/37))

__device__ float g_concat[BB*CONC];   // [64][812]: xm | hist
__device__ float g_h[BB*HID];         // [64][400]
__device__ float g_hid[BB*1400];      // [64][600 st | 400 age | 400 gen]

// ---------------- init xm region with base bias ----------------
__global__ void init_xm(const float* __restrict__ bias) {
    int i = blockIdx.x * blockDim.x + threadIdx.x;
    if (i < BB * EMB) {
        int b = i / EMB, n = i % EMB;
        g_concat[b * CONC + n] = bias[n];
    }
}

// ---------------- per-(b,c) histogram, torch.histc semantics ----------------
__global__ __launch_bounds__(256) void hist_kernel(const float* __restrict__ x) {
    int r = blockIdx.x;                      // 0..191  (b*3 + c)
    const float* row = x + (size_t)r * HWP;
    __shared__ float s_red[20];
    __shared__ int   s_bins[8][100];
    int t = threadIdx.x;
    int w = t >> 5, lane = t & 31;

    float mn = 1e30f, mx = -1e30f;
    for (int i = t; i < HWP; i += 256) {
        float v = row[i];
        mn = fminf(mn, v); mx = fmaxf(mx, v);
    }
    for (int o = 16; o > 0; o >>= 1) {
        mn = fminf(mn, __shfl_xor_sync(0xffffffffu, mn, o));
        mx = fmaxf(mx, __shfl_xor_sync(0xffffffffu, mx, o));
    }
    if (lane == 0) { s_red[w] = mn; s_red[8 + w] = mx; }
    for (int i = t; i < 800; i += 256) s_bins[0][i] = 0;   // flat zero (8*100)
    __syncthreads();
    if (t == 0) {
        float a = s_red[0], b = s_red[8];
        for (int k = 1; k < 8; k++) { a = fminf(a, s_red[k]); b = fmaxf(b, s_red[8 + k]); }
        s_red[16] = a; s_red[17] = b;
    }
    __syncthreads();
    float mnv = s_red[16], mxv = s_red[17];
    float width = (mxv > mnv) ? (mxv - mnv) : 1.0f;

    for (int i = t; i < HWP; i += 256) {
        float v = row[i];
        int idx = (int)floorf((v - mnv) / width * 100.0f);
        idx = idx < 0 ? 0 : (idx > 99 ? 99 : idx);
        atomicAdd(&s_bins[w][idx], 1);
    }
    __syncthreads();
    if (t < 100) {
        int s = 0;
        #pragma unroll
        for (int k = 0; k < 8; k++) s += s_bins[k][t];
        int b = r / 3, c = r % 3;
        g_concat[b * CONC + EMB + c * 100 + t] = (float)s;
    }
}

// ---------------- big GEMM: xm += x[64,150528] @ base_W.T[:,n0:n0+64] ----------------
__global__ __launch_bounds__(256, 2) void gemm1(const float* __restrict__ x,
                                                const float* __restrict__ W) {
    __shared__ float xs[64 * KTP];
    __shared__ float ws[64 * KTP];
    int n0 = blockIdx.x * 64;
    int tile0 = blockIdx.y * TPB_K;
    int tile1 = tile0 + TPB_K; if (tile1 > NTILES_K) tile1 = NTILES_K;

    int t  = threadIdx.x;
    int tn = t & 15;       // n lane (rows tn, tn+16, tn+32, tn+48)
    int tb = t >> 4;       // b lane
    int lr = t >> 4;       // load row base
    int lc = t & 15;       // load float4 col

    unsigned long long acc[4][4];
    #pragma unroll
    for (int i = 0; i < 4; i++)
        #pragma unroll
        for (int j = 0; j < 4; j++) acc[i][j] = 0ULL;

    for (int tile = tile0; tile < tile1; ++tile) {
        int k0 = tile * KT;
        #pragma unroll
        for (int rr = 0; rr < 4; ++rr) {
            int row = lr + rr * 16;
            float4 xv = *(const float4*)(x + (size_t)row * KBIG + k0 + lc * 4);
            *(float4*)(&xs[row * KTP + lc * 4]) = xv;
            float4 wv = *(const float4*)(W + (size_t)(n0 + row) * KBIG + k0 + lc * 4);
            *(float4*)(&ws[row * KTP + lc * 4]) = wv;
        }
        __syncthreads();
        #pragma unroll
        for (int kk = 0; kk < 16; ++kk) {
            ulonglong2 xv[4], wv[4];
            #pragma unroll
            for (int i = 0; i < 4; i++)
                xv[i] = *(const ulonglong2*)(&xs[(tb + 16 * i) * KTP + kk * 4]);
            #pragma unroll
            for (int j = 0; j < 4; j++)
                wv[j] = *(const ulonglong2*)(&ws[(tn + 16 * j) * KTP + kk * 4]);
            #pragma unroll
            for (int i = 0; i < 4; i++)
                #pragma unroll
                for (int j = 0; j < 4; j++) {
                    asm("fma.rn.f32x2 %0, %1, %2, %0;" : "+l"(acc[i][j]) : "l"(xv[i].x), "l"(wv[j].x));
                    asm("fma.rn.f32x2 %0, %1, %2, %0;" : "+l"(acc[i][j]) : "l"(xv[i].y), "l"(wv[j].y));
                }
        }
        __syncthreads();
    }
    #pragma unroll
    for (int i = 0; i < 4; i++) {
        int b = tb + 16 * i;
        #pragma unroll
        for (int j = 0; j < 4; j++) {
            int n = n0 + tn + 16 * j;
            unsigned lo = (unsigned)(acc[i][j] & 0xffffffffu);
            unsigned hi = (unsigned)(acc[i][j] >> 32);
            float v = __uint_as_float(lo) + __uint_as_float(hi);
            atomicAdd(&g_concat[b * CONC + n], v);
        }
    }
}

// ---------------- generic small GEMM: out = relu(in @ W.T + bias) ----------------
__global__ __launch_bounds__(256) void small_gemm(const float* __restrict__ in, int in_stride, int K,
                                                  const float* __restrict__ Wt, const float* __restrict__ bias,
                                                  float* __restrict__ out, int out_stride, int N) {
    __shared__ float is[16][33];
    __shared__ float wsm[16][33];
    int n0 = blockIdx.x * 16;
    int b0 = blockIdx.y * 16;
    int t = threadIdx.x;
    int ti = t & 15;    // n
    int tj = t >> 4;    // b
    float acc = 0.f;
    for (int k0 = 0; k0 < K; k0 += 32) {
        #pragma unroll
        for (int e = 0; e < 2; e++) {
            int idx = t + e * 256;
            int row = idx >> 5, col = idx & 31;
            float iv = (k0 + col < K) ? in[(size_t)(b0 + row) * in_stride + k0 + col] : 0.f;
            is[row][col] = iv;
            float wv = (n0 + row < N && k0 + col < K) ? Wt[(size_t)(n0 + row) * K + k0 + col] : 0.f;
            wsm[row][col] = wv;
        }
        __syncthreads();
        #pragma unroll
        for (int kk = 0; kk < 32; kk++) acc += is[tj][kk] * wsm[ti][kk];
        __syncthreads();
    }
    int n = n0 + ti;
    if (n < N)
        out[(size_t)(b0 + tj) * out_stride + n] = fmaxf(acc + bias[n], 0.f);
}

// ---------------- fused heads: 16 logits + relu + 3 softmaxes ----------------
__global__ __launch_bounds__(256) void heads_kernel(const float* __restrict__ stW2, const float* __restrict__ stb2,
                                                    const float* __restrict__ ageW2, const float* __restrict__ ageb2,
                                                    const float* __restrict__ genW2, const float* __restrict__ genb2,
                                                    float* __restrict__ out) {
    int b = blockIdx.x;
    __shared__ float sh[1400];
    __shared__ float slog[16];
    int t = threadIdx.x;
    for (int i = t; i < 1400; i += 256) sh[i] = g_hid[b * 1400 + i];
    __syncthreads();
    int w = t >> 5, lane = t & 31;
    for (int l = w; l < 16; l += 8) {
        const float* wr; const float* basep; int len; float bv;
        if (l < 10)      { wr = stW2  + l * 600;        basep = sh;        len = 600; bv = stb2[l]; }
        else if (l < 14) { wr = ageW2 + (l - 10) * 400; basep = sh + 600;  len = 400; bv = ageb2[l - 10]; }
        else             { wr = genW2 + (l - 14) * 400; basep = sh + 1000; len = 400; bv = genb2[l - 14]; }
        float s = 0.f;
        for (int i = lane; i < len; i += 32) s += basep[i] * wr[i];
        for (int o = 16; o > 0; o >>= 1) s += __shfl_xor_sync(0xffffffffu, s, o);
        if (lane == 0) slog[l] = fmaxf(s + bv, 0.f);
    }
    __syncthreads();
    if (t == 0) {
        float m = slog[0];
        for (int i = 1; i < 10; i++) m = fmaxf(m, slog[i]);
        float e[10], sum = 0.f;
        for (int i = 0; i < 10; i++) { e[i] = expf(slog[i] - m); sum += e[i]; }
        for (int i = 0; i < 10; i++) out[b * 10 + i] = e[i] / sum;
    } else if (t == 32) {
        float m = slog[10];
        for (int i = 11; i < 14; i++) m = fmaxf(m, slog[i]);
        float e[4], sum = 0.f;
        for (int i = 0; i < 4; i++) { e[i] = expf(slog[10 + i] - m); sum += e[i]; }
        for (int i = 0; i < 4; i++) out[640 + b * 4 + i] = e[i] / sum;
    } else if (t == 64) {
        float m = fmaxf(slog[14], slog[15]);
        float e0 = expf(slog[14] - m), e1 = expf(slog[15] - m);
        float inv = 1.f / (e0 + e1);
        out[896 + b * 2]     = e0 * inv;
        out[896 + b * 2 + 1] = e1 * inv;
    }
}

extern "C" void kernel_launch(void* const* d_in, const int* in_sizes, int n_in,
                              void* d_out, int out_size) {
    const float* x      = (const float*)d_in[0];
    const float* base_W = (const float*)d_in[1];
    const float* base_b = (const float*)d_in[2];
    const float* hW     = (const float*)d_in[3];
    const float* hb     = (const float*)d_in[4];
    const float* stW1   = (const float*)d_in[5];
    const float* stb1   = (const float*)d_in[6];
    const float* stW2   = (const float*)d_in[7];
    const float* stb2   = (const float*)d_in[8];
    const float* ageW1  = (const float*)d_in[9];
    const float* ageb1  = (const float*)d_in[10];
    const float* ageW2  = (const float*)d_in[11];
    const float* ageb2  = (const float*)d_in[12];
    const float* genW1  = (const float*)d_in[13];
    const float* genb1  = (const float*)d_in[14];
    const float* genW2  = (const float*)d_in[15];
    const float* genb2  = (const float*)d_in[16];
    float* out = (float*)d_out;

    float *pc = nullptr, *ph = nullptr, *phid = nullptr;
    cudaGetSymbolAddress((void**)&pc,   g_concat);
    cudaGetSymbolAddress((void**)&ph,   g_h);
    cudaGetSymbolAddress((void**)&phid, g_hid);

    init_xm<<<(BB * EMB + 255) / 256, 256>>>(base_b);
    hist_kernel<<<BB * CHN, 256>>>(x);
    gemm1<<<dim3(8, KSPLIT), 256>>>(x, base_W);

    // h = relu([xm|hist] @ hW.T + hb)   K=812 -> N=400
    small_gemm<<<dim3(25, 4), 256>>>(pc, CONC, CONC, hW, hb, ph, HID, HID);
    // three first-layer heads into g_hid
    small_gemm<<<dim3(38, 4), 256>>>(ph, HID, HID, stW1,  stb1,  phid,        1400, 600);
    small_gemm<<<dim3(25, 4), 256>>>(ph, HID, HID, ageW1, ageb1, phid + 600,  1400, 400);
    small_gemm<<<dim3(25, 4), 256>>>(ph, HID, HID, genW1, genb1, phid + 1000, 1400, 400);

    heads_kernel<<<BB, 256>>>(stW2, stb2, ageW2, ageb2, genW2, genb2, out);
}

// round 3
// speedup vs baseline: 1.2786x; 1.2786x over previous
#include <cuda_runtime.h>
#include <cstdint>

#define BB   64
#define CHN  3
#define HWP  (224*224)
#define KBIG (CHN*HWP)
#define EMB  512
#define CONC 812
#define HID  400

__device__ float g_concat[BB*CONC];   // [64][812]: xm | hist
__device__ float g_h[BB*HID];         // [64][400] pre-activation
__device__ float g_hid[BB*1400];      // [64][600|400|400] pre-activation

__device__ __forceinline__ uint32_t smem_u32(const void* p) {
    uint32_t a;
    asm("{ .reg .u64 t; cvta.to.shared.u64 t, %1; cvt.u32.u64 %0, t; }" : "=r"(a) : "l"(p));
    return a;
}

__device__ __forceinline__ void ldm4(uint32_t* r, uint32_t addr) {
    asm volatile("ldmatrix.sync.aligned.m8n8.x4.shared.b16 {%0,%1,%2,%3}, [%4];"
        : "=r"(r[0]), "=r"(r[1]), "=r"(r[2]), "=r"(r[3]) : "r"(addr));
}

__device__ __forceinline__ void mma16816(float* d, const uint32_t* a, const uint32_t* b) {
    asm volatile("mma.sync.aligned.m16n8k16.row.col.f32.bf16.bf16.f32 "
        "{%0,%1,%2,%3}, {%4,%5,%6,%7}, {%8,%9}, {%0,%1,%2,%3};"
        : "+f"(d[0]), "+f"(d[1]), "+f"(d[2]), "+f"(d[3])
        : "r"(a[0]), "r"(a[1]), "r"(a[2]), "r"(a[3]), "r"(b[0]), "r"(b[1]));
}

// split fp32x4 -> bf16 hi pair + bf16 lo pair (k order preserved: lo halfword = lower k)
__device__ __forceinline__ void cvt_split(float4 v, uint32_t& h01, uint32_t& h23,
                                          uint32_t& l01, uint32_t& l23) {
    asm("cvt.rn.bf16x2.f32 %0, %1, %2;" : "=r"(h01) : "f"(v.y), "f"(v.x));
    asm("cvt.rn.bf16x2.f32 %0, %1, %2;" : "=r"(h23) : "f"(v.w), "f"(v.z));
    float r0 = v.x - __uint_as_float(h01 << 16);
    float r1 = v.y - __uint_as_float(h01 & 0xffff0000u);
    float r2 = v.z - __uint_as_float(h23 << 16);
    float r3 = v.w - __uint_as_float(h23 & 0xffff0000u);
    asm("cvt.rn.bf16x2.f32 %0, %1, %2;" : "=r"(l01) : "f"(r1), "f"(r0));
    asm("cvt.rn.bf16x2.f32 %0, %1, %2;" : "=r"(l23) : "f"(r3), "f"(r2));
}

// ============ big GEMM: concat[b, n] += x[b,:] . W[n,:]  (bf16 3-term split, HMMA) ============
// grid (8 n-tiles of 64, 37 k-splits), 256 threads, 2 CTA/SM.
__global__ __launch_bounds__(256, 2) void gemm1(const float* __restrict__ x,
                                                const float* __restrict__ W) {
    __shared__ __align__(128) uint8_t smraw[32768];
    uint32_t base = smem_u32(smraw);
    const uint32_t XHI = base, XLO = base + 8192, WHI = base + 16384, WLO = base + 24576;

    int tid = threadIdx.x, wid = tid >> 5, lane = tid & 31;
    int warp_m = wid & 1;        // 0/1 -> batch rows 0-31 / 32-63
    int warp_n = wid >> 1;       // 0..3 -> n cols 16*warp_n
    int n0 = blockIdx.x * 64;
    int ky = blockIdx.y;
    int t0 = ky * 63 + (ky < 21 ? ky : 21);
    int cnt = 63 + (ky < 21 ? 1 : 0);

    int lrow = tid >> 4, lc4 = tid & 15;

    // ldmatrix lane addressing
    int ar = lane & 7, ag = lane >> 3;
    int a_row_off = (ag & 1) * 8 + ar;     // within m16
    int a_col_off = (ag >> 1) * 16;        // bytes
    int b_row_off = (ag >> 1) * 8 + ar;    // within n16
    int b_col_off = (ag & 1) * 16;

    float acc[2][2][4];
    #pragma unroll
    for (int i = 0; i < 2; i++)
        #pragma unroll
        for (int j = 0; j < 2; j++)
            #pragma unroll
            for (int q = 0; q < 4; q++) acc[i][j][q] = 0.f;

    for (int it = 0; it < cnt; ++it) {
        size_t k0 = (size_t)(t0 + it) * 64;
        float4 xv[4], wv[4];
        #pragma unroll
        for (int e = 0; e < 4; e++) {
            int i = tid + e * 256; int row = i >> 4, c4 = i & 15;
            xv[e] = *(const float4*)(x + (size_t)row * KBIG + k0 + c4 * 4);
            wv[e] = *(const float4*)(W + (size_t)(n0 + row) * KBIG + k0 + c4 * 4);
        }
        __syncthreads();   // previous tile's mma reads done
        #pragma unroll
        for (int e = 0; e < 4; e++) {
            int i = tid + e * 256; int row = i >> 4, c4 = i & 15;
            uint32_t off = row * 128 + ((c4 * 8) ^ ((row & 7) << 4));
            uint32_t h01, h23, l01, l23;
            cvt_split(xv[e], h01, h23, l01, l23);
            asm volatile("st.shared.v2.b32 [%0], {%1, %2};" :: "r"(XHI + off), "r"(h01), "r"(h23));
            asm volatile("st.shared.v2.b32 [%0], {%1, %2};" :: "r"(XLO + off), "r"(l01), "r"(l23));
            cvt_split(wv[e], h01, h23, l01, l23);
            asm volatile("st.shared.v2.b32 [%0], {%1, %2};" :: "r"(WHI + off), "r"(h01), "r"(h23));
            asm volatile("st.shared.v2.b32 [%0], {%1, %2};" :: "r"(WLO + off), "r"(l01), "r"(l23));
        }
        __syncthreads();
        #pragma unroll
        for (int ks = 0; ks < 4; ++ks) {
            int cbase = ks * 32;
            uint32_t ah[2][4], al[2][4], bh[4], bl[4];
            #pragma unroll
            for (int mi = 0; mi < 2; mi++) {
                int r = warp_m * 32 + mi * 16 + a_row_off;
                uint32_t col = (uint32_t)(cbase + a_col_off) ^ ((r & 7) << 4);
                ldm4(ah[mi], XHI + r * 128 + col);
                ldm4(al[mi], XLO + r * 128 + col);
            }
            {
                int r = warp_n * 16 + b_row_off;
                uint32_t col = (uint32_t)(cbase + b_col_off) ^ ((r & 7) << 4);
                ldm4(bh, WHI + r * 128 + col);
                ldm4(bl, WLO + r * 128 + col);
            }
            #pragma unroll
            for (int mi = 0; mi < 2; mi++)
                #pragma unroll
                for (int ni = 0; ni < 2; ni++) {
                    mma16816(acc[mi][ni], ah[mi], bh + ni * 2);
                    mma16816(acc[mi][ni], ah[mi], bl + ni * 2);
                    mma16816(acc[mi][ni], al[mi], bh + ni * 2);
                }
        }
    }

    // epilogue: atomic accumulate into bias-initialized concat
    #pragma unroll
    for (int mi = 0; mi < 2; mi++) {
        int b = warp_m * 32 + mi * 16 + (lane >> 2);
        #pragma unroll
        for (int ni = 0; ni < 2; ni++) {
            int n = n0 + warp_n * 16 + ni * 8 + (lane & 3) * 2;
            atomicAdd(&g_concat[b * CONC + n],           acc[mi][ni][0]);
            atomicAdd(&g_concat[b * CONC + n + 1],       acc[mi][ni][1]);
            atomicAdd(&g_concat[(b + 8) * CONC + n],     acc[mi][ni][2]);
            atomicAdd(&g_concat[(b + 8) * CONC + n + 1], acc[mi][ni][3]);
        }
    }
}

// ======================= init: biases into accumulators =======================
__global__ void init_all(const float* __restrict__ bb, const float* __restrict__ hb,
                         const float* __restrict__ stb1, const float* __restrict__ ageb1,
                         const float* __restrict__ genb1) {
    int i = blockIdx.x * 256 + threadIdx.x;
    if (i < BB * EMB) {
        g_concat[(i >> 9) * CONC + (i & 511)] = bb[i & 511];
        return;
    }
    int j = i - BB * EMB;
    if (j < BB * HID) { g_h[j] = hb[j % HID]; return; }
    int k2 = j - BB * HID;
    if (k2 < BB * 1400) {
        int c = k2 % 1400;
        float v = (c < 600) ? stb1[c] : (c < 1000 ? ageb1[c - 600] : genb1[c - 1000]);
        g_hid[k2] = v;
    }
}

// ======================= histogram (torch.histc semantics) =======================
__global__ __launch_bounds__(256) void hist_kernel(const float* __restrict__ x) {
    int r = blockIdx.x;
    const float* row = x + (size_t)r * HWP;
    __shared__ float s_red[20];
    __shared__ int   s_bins[8][100];
    int t = threadIdx.x;
    int w = t >> 5, lane = t & 31;

    float mn = 1e30f, mx = -1e30f;
    for (int i = t; i < HWP; i += 256) {
        float v = row[i];
        mn = fminf(mn, v); mx = fmaxf(mx, v);
    }
    for (int o = 16; o > 0; o >>= 1) {
        mn = fminf(mn, __shfl_xor_sync(0xffffffffu, mn, o));
        mx = fmaxf(mx, __shfl_xor_sync(0xffffffffu, mx, o));
    }
    if (lane == 0) { s_red[w] = mn; s_red[8 + w] = mx; }
    for (int i = t; i < 800; i += 256) s_bins[0][i] = 0;
    __syncthreads();
    if (t == 0) {
        float a = s_red[0], b = s_red[8];
        for (int k = 1; k < 8; k++) { a = fminf(a, s_red[k]); b = fmaxf(b, s_red[8 + k]); }
        s_red[16] = a; s_red[17] = b;
    }
    __syncthreads();
    float mnv = s_red[16], mxv = s_red[17];
    float width = (mxv > mnv) ? (mxv - mnv) : 1.0f;

    for (int i = t; i < HWP; i += 256) {
        float v = row[i];
        int idx = (int)floorf((v - mnv) / width * 100.0f);
        idx = idx < 0 ? 0 : (idx > 99 ? 99 : idx);
        atomicAdd(&s_bins[w][idx], 1);
    }
    __syncthreads();
    if (t < 100) {
        int s = 0;
        #pragma unroll
        for (int k = 0; k < 8; k++) s += s_bins[k][t];
        int b = r / 3, c = r % 3;
        g_concat[b * CONC + EMB + c * 100 + t] = (float)s;
    }
}

// ============ mid GEMM: out[b,n] += act(in[b,:]) . Wt[n,:] (K-split atomics) ============
__global__ __launch_bounds__(256) void mid_gemm(const float* __restrict__ in, int istride, int Kfull,
                                                const float* __restrict__ Wt,
                                                float* __restrict__ out, int ostride, int N,
                                                int klen, int relu_in) {
    __shared__ float is[64][33];
    __shared__ float ws[64][33];
    int n0 = blockIdx.x * 64;
    int kstart = blockIdx.y * klen;
    int kend = kstart + klen; if (kend > Kfull) kend = Kfull;
    int t = threadIdx.x;
    int tn = t & 15, tb = t >> 4;
    float acc[4][4] = {};
    for (int k0 = kstart; k0 < kend; k0 += 32) {
        #pragma unroll
        for (int e = 0; e < 8; e++) {
            int idx = t + e * 256;
            int row = idx >> 5, col = idx & 31;
            float iv = (k0 + col < Kfull) ? in[(size_t)row * istride + k0 + col] : 0.f;
            if (relu_in) iv = fmaxf(iv, 0.f);
            is[row][col] = iv;
            int n = n0 + row;
            ws[row][col] = (n < N && k0 + col < Kfull) ? Wt[(size_t)n * Kfull + k0 + col] : 0.f;
        }
        __syncthreads();
        #pragma unroll
        for (int kk = 0; kk < 32; kk++) {
            float xv[4], wv[4];
            #pragma unroll
            for (int i2 = 0; i2 < 4; i2++) xv[i2] = is[tb + 16 * i2][kk];
            #pragma unroll
            for (int j = 0; j < 4; j++) wv[j] = ws[tn + 16 * j][kk];
            #pragma unroll
            for (int i2 = 0; i2 < 4; i2++)
                #pragma unroll
                for (int j = 0; j < 4; j++) acc[i2][j] += xv[i2] * wv[j];
        }
        __syncthreads();
    }
    #pragma unroll
    for (int i2 = 0; i2 < 4; i2++) {
        int b = tb + 16 * i2;
        #pragma unroll
        for (int j = 0; j < 4; j++) {
            int n = n0 + tn + 16 * j;
            if (n < N) atomicAdd(&out[(size_t)b * ostride + n], acc[i2][j]);
        }
    }
}

// ================= fused heads: relu(hid) -> 16 logits + relu + 3 softmaxes =================
__global__ __launch_bounds__(256) void heads_kernel(const float* __restrict__ stW2, const float* __restrict__ stb2,
                                                    const float* __restrict__ ageW2, const float* __restrict__ ageb2,
                                                    const float* __restrict__ genW2, const float* __restrict__ genb2,
                                                    float* __restrict__ out) {
    int b = blockIdx.x;
    __shared__ float sh[1400];
    __shared__ float slog[16];
    int t = threadIdx.x;
    for (int i = t; i < 1400; i += 256) sh[i] = fmaxf(g_hid[b * 1400 + i], 0.f);
    __syncthreads();
    int w = t >> 5, lane = t & 31;
    for (int l = w; l < 16; l += 8) {
        const float* wr; const float* basep; int len; float bv;
        if (l < 10)      { wr = stW2  + l * 600;        basep = sh;        len = 600; bv = stb2[l]; }
        else if (l < 14) { wr = ageW2 + (l - 10) * 400; basep = sh + 600;  len = 400; bv = ageb2[l - 10]; }
        else             { wr = genW2 + (l - 14) * 400; basep = sh + 1000; len = 400; bv = genb2[l - 14]; }
        float s = 0.f;
        for (int i = lane; i < len; i += 32) s += basep[i] * wr[i];
        for (int o = 16; o > 0; o >>= 1) s += __shfl_xor_sync(0xffffffffu, s, o);
        if (lane == 0) slog[l] = fmaxf(s + bv, 0.f);
    }
    __syncthreads();
    if (t == 0) {
        float m = slog[0];
        for (int i = 1; i < 10; i++) m = fmaxf(m, slog[i]);
        float e[10], sum = 0.f;
        for (int i = 0; i < 10; i++) { e[i] = expf(slog[i] - m); sum += e[i]; }
        for (int i = 0; i < 10; i++) out[b * 10 + i] = e[i] / sum;
    } else if (t == 32) {
        float m = slog[10];
        for (int i = 11; i < 14; i++) m = fmaxf(m, slog[i]);
        float e[4], sum = 0.f;
        for (int i = 0; i < 4; i++) { e[i] = expf(slog[10 + i] - m); sum += e[i]; }
        for (int i = 0; i < 4; i++) out[640 + b * 4 + i] = e[i] / sum;
    } else if (t == 64) {
        float m = fmaxf(slog[14], slog[15]);
        float e0 = expf(slog[14] - m), e1 = expf(slog[15] - m);
        float inv = 1.f / (e0 + e1);
        out[896 + b * 2]     = e0 * inv;
        out[896 + b * 2 + 1] = e1 * inv;
    }
}

extern "C" void kernel_launch(void* const* d_in, const int* in_sizes, int n_in,
                              void* d_out, int out_size) {
    const float* x      = (const float*)d_in[0];
    const float* base_W = (const float*)d_in[1];
    const float* base_b = (const float*)d_in[2];
    const float* hW     = (const float*)d_in[3];
    const float* hb     = (const float*)d_in[4];
    const float* stW1   = (const float*)d_in[5];
    const float* stb1   = (const float*)d_in[6];
    const float* stW2   = (const float*)d_in[7];
    const float* stb2   = (const float*)d_in[8];
    const float* ageW1  = (const float*)d_in[9];
    const float* ageb1  = (const float*)d_in[10];
    const float* ageW2  = (const float*)d_in[11];
    const float* ageb2  = (const float*)d_in[12];
    const float* genW1  = (const float*)d_in[13];
    const float* genb1  = (const float*)d_in[14];
    const float* genW2  = (const float*)d_in[15];
    const float* genb2  = (const float*)d_in[16];
    float* out = (float*)d_out;

    float *pc = nullptr, *ph = nullptr, *phid = nullptr;
    cudaGetSymbolAddress((void**)&pc,   g_concat);
    cudaGetSymbolAddress((void**)&ph,   g_h);
    cudaGetSymbolAddress((void**)&phid, g_hid);

    init_all<<<(BB * (EMB + HID + 1400) + 255) / 256, 256>>>(base_b, hb, stb1, ageb1, genb1);
    hist_kernel<<<BB * CHN, 256>>>(x);
    gemm1<<<dim3(8, 37), 256>>>(x, base_W);

    // h_pre = concat @ hW.T + hb
    mid_gemm<<<dim3(7, 4), 256>>>(pc, CONC, CONC, hW, ph, HID, HID, 224, 0);
    // head layer-1 (relu applied to h on load)
    mid_gemm<<<dim3(10, 2), 256>>>(ph, HID, HID, stW1,  phid,        1400, 600, 224, 1);
    mid_gemm<<<dim3(7, 2),  256>>>(ph, HID, HID, ageW1, phid + 600,  1400, 400, 224, 1);
    mid_gemm<<<dim3(7, 2),  256>>>(ph, HID, HID, genW1, phid + 1000, 1400, 400, 224, 1);

    heads_kernel<<<BB, 256>>>(stW2, stb2, ageW2, ageb2, genW2, genb2, out);
}

// round 4
// speedup vs baseline: 2.3573x; 1.8437x over previous
#include <cuda_runtime.h>
#include <cstdint>

#define BB   64
#define CHN  3
#define HWP  (224*224)
#define KBIG (CHN*HWP)
#define EMB  512
#define CONC 812
#define HID  400

__device__ float g_concat[BB*CONC];   // [64][812]: xm | hist
__device__ float g_h[BB*HID];         // [64][400] pre-activation
__device__ float g_hid[BB*1400];      // [64][600|400|400] pre-activation
__device__ float g_mm[BB*CHN*2];      // per-(b,c) min/max

__device__ __forceinline__ uint32_t smem_u32(const void* p) {
    uint32_t a;
    asm("{ .reg .u64 t; cvta.to.shared.u64 t, %1; cvt.u32.u64 %0, t; }" : "=r"(a) : "l"(p));
    return a;
}

__device__ __forceinline__ void ldm4(uint32_t* r, uint32_t addr) {
    asm volatile("ldmatrix.sync.aligned.m8n8.x4.shared.b16 {%0,%1,%2,%3}, [%4];"
        : "=r"(r[0]), "=r"(r[1]), "=r"(r[2]), "=r"(r[3]) : "r"(addr));
}

__device__ __forceinline__ void mma16816(float* d, const uint32_t* a, const uint32_t* b) {
    asm volatile("mma.sync.aligned.m16n8k16.row.col.f32.bf16.bf16.f32 "
        "{%0,%1,%2,%3}, {%4,%5,%6,%7}, {%8,%9}, {%0,%1,%2,%3};"
        : "+f"(d[0]), "+f"(d[1]), "+f"(d[2]), "+f"(d[3])
        : "r"(a[0]), "r"(a[1]), "r"(a[2]), "r"(a[3]), "r"(b[0]), "r"(b[1]));
}

// split fp32x4 -> bf16 hi pair + bf16 lo pair
__device__ __forceinline__ void cvt_split(float4 v, uint32_t& h01, uint32_t& h23,
                                          uint32_t& l01, uint32_t& l23) {
    asm("cvt.rn.bf16x2.f32 %0, %1, %2;" : "=r"(h01) : "f"(v.y), "f"(v.x));
    asm("cvt.rn.bf16x2.f32 %0, %1, %2;" : "=r"(h23) : "f"(v.w), "f"(v.z));
    float r0 = v.x - __uint_as_float(h01 << 16);
    float r1 = v.y - __uint_as_float(h01 & 0xffff0000u);
    float r2 = v.z - __uint_as_float(h23 << 16);
    float r3 = v.w - __uint_as_float(h23 & 0xffff0000u);
    asm("cvt.rn.bf16x2.f32 %0, %1, %2;" : "=r"(l01) : "f"(r1), "f"(r0));
    asm("cvt.rn.bf16x2.f32 %0, %1, %2;" : "=r"(l23) : "f"(r3), "f"(r2));
}

// ============ big GEMM: concat[b, n] += x[b,:] . W[n,:]  (bf16 3-term split, HMMA) ============
__global__ __launch_bounds__(256, 2) void gemm1(const float* __restrict__ x,
                                                const float* __restrict__ W) {
    __shared__ __align__(128) uint8_t smraw[32768];
    uint32_t base = smem_u32(smraw);
    const uint32_t XHI = base, XLO = base + 8192, WHI = base + 16384, WLO = base + 24576;

    int tid = threadIdx.x, wid = tid >> 5, lane = tid & 31;
    int warp_m = wid & 1;
    int warp_n = wid >> 1;
    int n0 = blockIdx.x * 64;
    int ky = blockIdx.y;
    int t0 = ky * 63 + (ky < 21 ? ky : 21);
    int cnt = 63 + (ky < 21 ? 1 : 0);

    int ar = lane & 7, ag = lane >> 3;
    int a_row_off = (ag & 1) * 8 + ar;
    int a_col_off = (ag >> 1) * 16;
    int b_row_off = (ag >> 1) * 8 + ar;
    int b_col_off = (ag & 1) * 16;

    float acc[2][2][4];
    #pragma unroll
    for (int i = 0; i < 2; i++)
        #pragma unroll
        for (int j = 0; j < 2; j++)
            #pragma unroll
            for (int q = 0; q < 4; q++) acc[i][j][q] = 0.f;

    for (int it = 0; it < cnt; ++it) {
        size_t k0 = (size_t)(t0 + it) * 64;
        float4 xv[4], wv[4];
        #pragma unroll
        for (int e = 0; e < 4; e++) {
            int i = tid + e * 256; int row = i >> 4, c4 = i & 15;
            xv[e] = *(const float4*)(x + (size_t)row * KBIG + k0 + c4 * 4);
            wv[e] = *(const float4*)(W + (size_t)(n0 + row) * KBIG + k0 + c4 * 4);
        }
        __syncthreads();
        #pragma unroll
        for (int e = 0; e < 4; e++) {
            int i = tid + e * 256; int row = i >> 4, c4 = i & 15;
            uint32_t off = row * 128 + ((c4 * 8) ^ ((row & 7) << 4));
            uint32_t h01, h23, l01, l23;
            cvt_split(xv[e], h01, h23, l01, l23);
            asm volatile("st.shared.v2.b32 [%0], {%1, %2};" :: "r"(XHI + off), "r"(h01), "r"(h23));
            asm volatile("st.shared.v2.b32 [%0], {%1, %2};" :: "r"(XLO + off), "r"(l01), "r"(l23));
            cvt_split(wv[e], h01, h23, l01, l23);
            asm volatile("st.shared.v2.b32 [%0], {%1, %2};" :: "r"(WHI + off), "r"(h01), "r"(h23));
            asm volatile("st.shared.v2.b32 [%0], {%1, %2};" :: "r"(WLO + off), "r"(l01), "r"(l23));
        }
        __syncthreads();
        #pragma unroll
        for (int ks = 0; ks < 4; ++ks) {
            int cbase = ks * 32;
            uint32_t ah[2][4], al[2][4], bh[4], bl[4];
            #pragma unroll
            for (int mi = 0; mi < 2; mi++) {
                int r = warp_m * 32 + mi * 16 + a_row_off;
                uint32_t col = (uint32_t)(cbase + a_col_off) ^ ((r & 7) << 4);
                ldm4(ah[mi], XHI + r * 128 + col);
                ldm4(al[mi], XLO + r * 128 + col);
            }
            {
                int r = warp_n * 16 + b_row_off;
                uint32_t col = (uint32_t)(cbase + b_col_off) ^ ((r & 7) << 4);
                ldm4(bh, WHI + r * 128 + col);
                ldm4(bl, WLO + r * 128 + col);
            }
            #pragma unroll
            for (int mi = 0; mi < 2; mi++)
                #pragma unroll
                for (int ni = 0; ni < 2; ni++) {
                    mma16816(acc[mi][ni], ah[mi], bh + ni * 2);
                    mma16816(acc[mi][ni], ah[mi], bl + ni * 2);
                    mma16816(acc[mi][ni], al[mi], bh + ni * 2);
                }
        }
    }

    #pragma unroll
    for (int mi = 0; mi < 2; mi++) {
        int b = warp_m * 32 + mi * 16 + (lane >> 2);
        #pragma unroll
        for (int ni = 0; ni < 2; ni++) {
            int n = n0 + warp_n * 16 + ni * 8 + (lane & 3) * 2;
            atomicAdd(&g_concat[b * CONC + n],           acc[mi][ni][0]);
            atomicAdd(&g_concat[b * CONC + n + 1],       acc[mi][ni][1]);
            atomicAdd(&g_concat[(b + 8) * CONC + n],     acc[mi][ni][2]);
            atomicAdd(&g_concat[(b + 8) * CONC + n + 1], acc[mi][ni][3]);
        }
    }
}

// ======================= init kernels =======================
__global__ void init_concat(const float* __restrict__ bb) {
    int i = blockIdx.x * 256 + threadIdx.x;
    if (i < BB * EMB) g_concat[(i >> 9) * CONC + (i & 511)] = bb[i & 511];
}
__global__ void init_h(const float* __restrict__ hb) {
    int i = blockIdx.x * 256 + threadIdx.x;
    if (i < BB * HID) g_h[i] = hb[i % HID];
}
__global__ void init_hid(const float* __restrict__ stb1, const float* __restrict__ ageb1,
                         const float* __restrict__ genb1) {
    int i = blockIdx.x * 256 + threadIdx.x;
    if (i < BB * 1400) {
        int c = i % 1400;
        g_hid[i] = (c < 600) ? stb1[c] : (c < 1000 ? ageb1[c - 600] : genb1[c - 1000]);
    }
}

// ======================= histogram pass 1: min/max per (b,c) =======================
__global__ __launch_bounds__(256) void hist_minmax(const float* __restrict__ x) {
    int r = blockIdx.x;
    const float4* row = (const float4*)(x + (size_t)r * HWP);
    __shared__ float s_red[16];
    int t = threadIdx.x, w = t >> 5, lane = t & 31;
    float mn = 1e30f, mx = -1e30f;
    #pragma unroll 7
    for (int i = t; i < HWP / 4; i += 256) {
        float4 v = row[i];
        mn = fminf(mn, fminf(fminf(v.x, v.y), fminf(v.z, v.w)));
        mx = fmaxf(mx, fmaxf(fmaxf(v.x, v.y), fmaxf(v.z, v.w)));
    }
    for (int o = 16; o > 0; o >>= 1) {
        mn = fminf(mn, __shfl_xor_sync(0xffffffffu, mn, o));
        mx = fmaxf(mx, __shfl_xor_sync(0xffffffffu, mx, o));
    }
    if (lane == 0) { s_red[w] = mn; s_red[8 + w] = mx; }
    __syncthreads();
    if (t == 0) {
        float a = s_red[0], b = s_red[8];
        for (int k = 1; k < 8; k++) { a = fminf(a, s_red[k]); b = fmaxf(b, s_red[8 + k]); }
        g_mm[r * 2] = a; g_mm[r * 2 + 1] = b;
    }
}

// ======================= histogram pass 2: binning =======================
__global__ __launch_bounds__(256) void hist_bins(const float* __restrict__ x) {
    int r = blockIdx.x;
    const float4* row = (const float4*)(x + (size_t)r * HWP);
    __shared__ int s_bins[8][100];
    int t = threadIdx.x, w = t >> 5;
    for (int i = t; i < 800; i += 256) s_bins[0][i] = 0;
    __syncthreads();
    float mnv = g_mm[r * 2], mxv = g_mm[r * 2 + 1];
    float width = (mxv > mnv) ? (mxv - mnv) : 1.0f;
    float scale = 100.0f / width;
    for (int i = t; i < HWP / 4; i += 256) {
        float4 v = row[i];
        int i0 = (int)floorf((v.x - mnv) * scale);
        int i1 = (int)floorf((v.y - mnv) * scale);
        int i2 = (int)floorf((v.z - mnv) * scale);
        int i3 = (int)floorf((v.w - mnv) * scale);
        i0 = min(max(i0, 0), 99); i1 = min(max(i1, 0), 99);
        i2 = min(max(i2, 0), 99); i3 = min(max(i3, 0), 99);
        atomicAdd(&s_bins[w][i0], 1);
        atomicAdd(&s_bins[w][i1], 1);
        atomicAdd(&s_bins[w][i2], 1);
        atomicAdd(&s_bins[w][i3], 1);
    }
    __syncthreads();
    if (t < 100) {
        int s = 0;
        #pragma unroll
        for (int k = 0; k < 8; k++) s += s_bins[k][t];
        int b = r / 3, c = r % 3;
        g_concat[b * CONC + EMB + c * 100 + t] = (float)s;
    }
}

// ============ mid GEMM: out[b,n] += act(in[b,:]) . Wt[n,:] (fine K-split atomics) ============
__global__ __launch_bounds__(256) void mid_gemm(const float* __restrict__ in, int istride, int Kfull,
                                                const float* __restrict__ Wt,
                                                float* __restrict__ out, int ostride, int N,
                                                int relu_in) {
    __shared__ float is[64][33];
    __shared__ float ws[64][33];
    int n0 = blockIdx.x * 64;
    int k0 = blockIdx.y * 32;
    int t = threadIdx.x;
    int tn = t & 15, tb = t >> 4;
    float acc[4][4] = {};
    #pragma unroll
    for (int e = 0; e < 8; e++) {
        int idx = t + e * 256;
        int row = idx >> 5, col = idx & 31;
        float iv = (k0 + col < Kfull) ? in[(size_t)row * istride + k0 + col] : 0.f;
        if (relu_in) iv = fmaxf(iv, 0.f);
        is[row][col] = iv;
        int n = n0 + row;
        ws[row][col] = (n < N && k0 + col < Kfull) ? Wt[(size_t)n * Kfull + k0 + col] : 0.f;
    }
    __syncthreads();
    #pragma unroll
    for (int kk = 0; kk < 32; kk++) {
        float xv[4], wv[4];
        #pragma unroll
        for (int i2 = 0; i2 < 4; i2++) xv[i2] = is[tb + 16 * i2][kk];
        #pragma unroll
        for (int j = 0; j < 4; j++) wv[j] = ws[tn + 16 * j][kk];
        #pragma unroll
        for (int i2 = 0; i2 < 4; i2++)
            #pragma unroll
            for (int j = 0; j < 4; j++) acc[i2][j] += xv[i2] * wv[j];
    }
    #pragma unroll
    for (int i2 = 0; i2 < 4; i2++) {
        int b = tb + 16 * i2;
        #pragma unroll
        for (int j = 0; j < 4; j++) {
            int n = n0 + tn + 16 * j;
            if (n < N) atomicAdd(&out[(size_t)b * ostride + n], acc[i2][j]);
        }
    }
}

// ============ merged head layer-1: g_hid[b,n] += relu(g_h[b,:]) . W(n)[.,:] ============
__global__ __launch_bounds__(256) void heads1_gemm(const float* __restrict__ stW1,
                                                   const float* __restrict__ ageW1,
                                                   const float* __restrict__ genW1) {
    __shared__ float is[64][33];
    __shared__ float ws[64][33];
    int n0 = blockIdx.x * 64;
    int k0 = blockIdx.y * 32;
    int t = threadIdx.x;
    int tn = t & 15, tb = t >> 4;
    #pragma unroll
    for (int e = 0; e < 8; e++) {
        int idx = t + e * 256;
        int row = idx >> 5, col = idx & 31;
        float iv = (k0 + col < HID) ? fmaxf(g_h[(size_t)row * HID + k0 + col], 0.f) : 0.f;
        is[row][col] = iv;
        int n = n0 + row;
        float wv = 0.f;
        if (n < 1400 && k0 + col < HID) {
            const float* p = (n < 600) ? (stW1 + (size_t)n * HID)
                           : (n < 1000) ? (ageW1 + (size_t)(n - 600) * HID)
                                        : (genW1 + (size_t)(n - 1000) * HID);
            wv = p[k0 + col];
        }
        ws[row][col] = wv;
    }
    __syncthreads();
    float acc[4][4] = {};
    #pragma unroll
    for (int kk = 0; kk < 32; kk++) {
        float xv[4], wv[4];
        #pragma unroll
        for (int i2 = 0; i2 < 4; i2++) xv[i2] = is[tb + 16 * i2][kk];
        #pragma unroll
        for (int j = 0; j < 4; j++) wv[j] = ws[tn + 16 * j][kk];
        #pragma unroll
        for (int i2 = 0; i2 < 4; i2++)
            #pragma unroll
            for (int j = 0; j < 4; j++) acc[i2][j] += xv[i2] * wv[j];
    }
    #pragma unroll
    for (int i2 = 0; i2 < 4; i2++) {
        int b = tb + 16 * i2;
        #pragma unroll
        for (int j = 0; j < 4; j++) {
            int n = n0 + tn + 16 * j;
            if (n < 1400) atomicAdd(&g_hid[(size_t)b * 1400 + n], acc[i2][j]);
        }
    }
}

// ================= fused heads: relu(hid) -> 16 logits + relu + 3 softmaxes =================
__global__ __launch_bounds__(256) void heads_kernel(const float* __restrict__ stW2, const float* __restrict__ stb2,
                                                    const float* __restrict__ ageW2, const float* __restrict__ ageb2,
                                                    const float* __restrict__ genW2, const float* __restrict__ genb2,
                                                    float* __restrict__ out) {
    int b = blockIdx.x;
    __shared__ float sh[1400];
    __shared__ float slog[16];
    int t = threadIdx.x;
    for (int i = t; i < 1400; i += 256) sh[i] = fmaxf(g_hid[b * 1400 + i], 0.f);
    __syncthreads();
    int w = t >> 5, lane = t & 31;
    for (int l = w; l < 16; l += 8) {
        const float* wr; const float* basep; int len; float bv;
        if (l < 10)      { wr = stW2  + l * 600;        basep = sh;        len = 600; bv = stb2[l]; }
        else if (l < 14) { wr = ageW2 + (l - 10) * 400; basep = sh + 600;  len = 400; bv = ageb2[l - 10]; }
        else             { wr = genW2 + (l - 14) * 400; basep = sh + 1000; len = 400; bv = genb2[l - 14]; }
        float s = 0.f;
        for (int i = lane; i < len; i += 32) s += basep[i] * wr[i];
        for (int o = 16; o > 0; o >>= 1) s += __shfl_xor_sync(0xffffffffu, s, o);
        if (lane == 0) slog[l] = fmaxf(s + bv, 0.f);
    }
    __syncthreads();
    if (t == 0) {
        float m = slog[0];
        for (int i = 1; i < 10; i++) m = fmaxf(m, slog[i]);
        float e[10], sum = 0.f;
        for (int i = 0; i < 10; i++) { e[i] = expf(slog[i] - m); sum += e[i]; }
        for (int i = 0; i < 10; i++) out[b * 10 + i] = e[i] / sum;
    } else if (t == 32) {
        float m = slog[10];
        for (int i = 11; i < 14; i++) m = fmaxf(m, slog[i]);
        float e[4], sum = 0.f;
        for (int i = 0; i < 4; i++) { e[i] = expf(slog[10 + i] - m); sum += e[i]; }
        for (int i = 0; i < 4; i++) out[640 + b * 4 + i] = e[i] / sum;
    } else if (t == 64) {
        float m = fmaxf(slog[14], slog[15]);
        float e0 = expf(slog[14] - m), e1 = expf(slog[15] - m);
        float inv = 1.f / (e0 + e1);
        out[896 + b * 2]     = e0 * inv;
        out[896 + b * 2 + 1] = e1 * inv;
    }
}

extern "C" void kernel_launch(void* const* d_in, const int* in_sizes, int n_in,
                              void* d_out, int out_size) {
    const float* x      = (const float*)d_in[0];
    const float* base_W = (const float*)d_in[1];
    const float* base_b = (const float*)d_in[2];
    const float* hW     = (const float*)d_in[3];
    const float* hb     = (const float*)d_in[4];
    const float* stW1   = (const float*)d_in[5];
    const float* stb1   = (const float*)d_in[6];
    const float* stW2   = (const float*)d_in[7];
    const float* stb2   = (const float*)d_in[8];
    const float* ageW1  = (const float*)d_in[9];
    const float* ageb1  = (const float*)d_in[10];
    const float* ageW2  = (const float*)d_in[11];
    const float* ageb2  = (const float*)d_in[12];
    const float* genW1  = (const float*)d_in[13];
    const float* genb1  = (const float*)d_in[14];
    const float* genW2  = (const float*)d_in[15];
    const float* genb2  = (const float*)d_in[16];
    float* out = (float*)d_out;

    float *pc = nullptr, *ph = nullptr;
    cudaGetSymbolAddress((void**)&pc, g_concat);
    cudaGetSymbolAddress((void**)&ph, g_h);

    // launches 1-5 (so -s 5 captures gemm1)
    init_concat<<<(BB * EMB + 255) / 256, 256>>>(base_b);
    init_h<<<(BB * HID + 255) / 256, 256>>>(hb);
    init_hid<<<(BB * 1400 + 255) / 256, 256>>>(stb1, ageb1, genb1);
    hist_minmax<<<BB * CHN, 256>>>(x);
    hist_bins<<<BB * CHN, 256>>>(x);
    // launch 6: the big one
    gemm1<<<dim3(8, 37), 256>>>(x, base_W);

    // h_pre = concat @ hW.T (+hb pre-initialized); K=812 -> 26 k-chunks of 32
    mid_gemm<<<dim3(7, 26), 256>>>(pc, CONC, CONC, hW, ph, HID, HID, 0);
    // merged head layer-1: N=1400, K=400 -> 13 k-chunks
    heads1_gemm<<<dim3(22, 13), 256>>>(stW1, ageW1, genW1);

    heads_kernel<<<BB, 256>>>(stW2, stb2, ageW2, ageb2, genW2, genb2, out);
}

// round 5
// speedup vs baseline: 2.3965x; 1.0166x over previous
#include <cuda_runtime.h>
#include <cstdint>

#define BB   64
#define CHN  3
#define HWP  (224*224)
#define KBIG (CHN*HWP)
#define EMB  512
#define CONC 812
#define HID  400

__device__ float g_concat[BB*CONC];   // [64][812]: xm | hist
__device__ float g_h[BB*HID];         // [64][400] pre-activation
__device__ float g_hid[BB*1400];      // [64][600|400|400] pre-activation

__device__ __forceinline__ uint32_t smem_u32(const void* p) {
    uint32_t a;
    asm("{ .reg .u64 t; cvta.to.shared.u64 t, %1; cvt.u32.u64 %0, t; }" : "=r"(a) : "l"(p));
    return a;
}

__device__ __forceinline__ void ldm4(uint32_t* r, uint32_t addr) {
    asm volatile("ldmatrix.sync.aligned.m8n8.x4.shared.b16 {%0,%1,%2,%3}, [%4];"
        : "=r"(r[0]), "=r"(r[1]), "=r"(r[2]), "=r"(r[3]) : "r"(addr));
}

__device__ __forceinline__ void mma16816(float* d, const uint32_t* a, const uint32_t* b) {
    asm volatile("mma.sync.aligned.m16n8k16.row.col.f32.bf16.bf16.f32 "
        "{%0,%1,%2,%3}, {%4,%5,%6,%7}, {%8,%9}, {%0,%1,%2,%3};"
        : "+f"(d[0]), "+f"(d[1]), "+f"(d[2]), "+f"(d[3])
        : "r"(a[0]), "r"(a[1]), "r"(a[2]), "r"(a[3]), "r"(b[0]), "r"(b[1]));
}

// split fp32x4 -> bf16 hi pair + bf16 lo pair (low halfword = lower k)
__device__ __forceinline__ void cvt_split(float4 v, uint32_t& h01, uint32_t& h23,
                                          uint32_t& l01, uint32_t& l23) {
    asm("cvt.rn.bf16x2.f32 %0, %1, %2;" : "=r"(h01) : "f"(v.y), "f"(v.x));
    asm("cvt.rn.bf16x2.f32 %0, %1, %2;" : "=r"(h23) : "f"(v.w), "f"(v.z));
    float r0 = v.x - __uint_as_float(h01 << 16);
    float r1 = v.y - __uint_as_float(h01 & 0xffff0000u);
    float r2 = v.z - __uint_as_float(h23 << 16);
    float r3 = v.w - __uint_as_float(h23 & 0xffff0000u);
    asm("cvt.rn.bf16x2.f32 %0, %1, %2;" : "=r"(l01) : "f"(r1), "f"(r0));
    asm("cvt.rn.bf16x2.f32 %0, %1, %2;" : "=r"(l23) : "f"(r3), "f"(r2));
}

// ===== big GEMM: concat[b,n] += x[b,:].W[n,:]  (bf16 3-term split, HMMA, 64x128 tile) =====
// grid (4 n-tiles of 128, 74 k-splits) = 296 CTAs, 2/SM.
#define KSPLIT 74
__global__ __launch_bounds__(256, 2) void gemm1(const float* __restrict__ x,
                                                const float* __restrict__ W) {
    __shared__ __align__(128) uint8_t smraw[49152];
    uint32_t base = smem_u32(smraw);
    const uint32_t XHI = base, XLO = base + 8192, WHI = base + 16384, WLO = base + 32768;

    int tid = threadIdx.x, wid = tid >> 5, lane = tid & 31;
    int warp_m = wid >> 2;       // 0/1 -> batch rows 0-31 / 32-63
    int warp_n = wid & 3;        // 0..3 -> n cols 32*warp_n
    int n0 = blockIdx.x * 128;
    int ky = blockIdx.y;
    int t0 = ky * 31 + (ky < 58 ? ky : 58);
    int cnt = 31 + (ky < 58 ? 1 : 0);

    int ar = lane & 7, ag = lane >> 3;
    int a_row_off = (ag & 1) * 8 + ar;
    int a_col_off = (ag >> 1) * 16;
    int b_row_off = (ag >> 1) * 8 + ar;
    int b_col_off = (ag & 1) * 16;

    float acc[2][4][4];
    #pragma unroll
    for (int i = 0; i < 2; i++)
        #pragma unroll
        for (int j = 0; j < 4; j++)
            #pragma unroll
            for (int q = 0; q < 4; q++) acc[i][j][q] = 0.f;

    int lrow = tid >> 4, lc4 = tid & 15;

    for (int it = 0; it < cnt; ++it) {
        size_t k0 = (size_t)(t0 + it) * 64;
        float4 xv[4], wv[8];
        #pragma unroll
        for (int e = 0; e < 4; e++) {
            int row = lrow + e * 16;
            xv[e] = *(const float4*)(x + (size_t)row * KBIG + k0 + lc4 * 4);
        }
        #pragma unroll
        for (int e = 0; e < 8; e++) {
            int row = lrow + e * 16;
            wv[e] = *(const float4*)(W + (size_t)(n0 + row) * KBIG + k0 + lc4 * 4);
        }
        __syncthreads();   // previous tile's mma reads done
        {
            uint32_t off0 = (uint32_t)(lrow * 128 + ((lc4 * 8) ^ ((lrow & 7) << 4)));
            #pragma unroll
            for (int e = 0; e < 4; e++) {
                uint32_t off = off0 + e * 2048;
                uint32_t h01, h23, l01, l23;
                cvt_split(xv[e], h01, h23, l01, l23);
                asm volatile("st.shared.v2.b32 [%0], {%1, %2};" :: "r"(XHI + off), "r"(h01), "r"(h23));
                asm volatile("st.shared.v2.b32 [%0], {%1, %2};" :: "r"(XLO + off), "r"(l01), "r"(l23));
            }
            #pragma unroll
            for (int e = 0; e < 8; e++) {
                uint32_t off = off0 + e * 2048;
                uint32_t h01, h23, l01, l23;
                cvt_split(wv[e], h01, h23, l01, l23);
                asm volatile("st.shared.v2.b32 [%0], {%1, %2};" :: "r"(WHI + off), "r"(h01), "r"(h23));
                asm volatile("st.shared.v2.b32 [%0], {%1, %2};" :: "r"(WLO + off), "r"(l01), "r"(l23));
            }
        }
        __syncthreads();
        #pragma unroll
        for (int ks = 0; ks < 4; ++ks) {
            int cbase = ks * 32;
            uint32_t ah[2][4], al[2][4], bh[2][4], bl[2][4];
            #pragma unroll
            for (int mi = 0; mi < 2; mi++) {
                int r = warp_m * 32 + mi * 16 + a_row_off;
                uint32_t col = (uint32_t)(cbase + a_col_off) ^ ((r & 7) << 4);
                ldm4(ah[mi], XHI + r * 128 + col);
                ldm4(al[mi], XLO + r * 128 + col);
            }
            #pragma unroll
            for (int ni = 0; ni < 2; ni++) {
                int r = warp_n * 32 + ni * 16 + b_row_off;
                uint32_t col = (uint32_t)(cbase + b_col_off) ^ ((r & 7) << 4);
                ldm4(bh[ni], WHI + r * 128 + col);
                ldm4(bl[ni], WLO + r * 128 + col);
            }
            #pragma unroll
            for (int mi = 0; mi < 2; mi++)
                #pragma unroll
                for (int ni = 0; ni < 2; ni++)
                    #pragma unroll
                    for (int nj = 0; nj < 2; nj++) {
                        float* d = acc[mi][ni * 2 + nj];
                        mma16816(d, ah[mi], bh[ni] + nj * 2);
                        mma16816(d, ah[mi], bl[ni] + nj * 2);
                        mma16816(d, al[mi], bh[ni] + nj * 2);
                    }
        }
    }

    #pragma unroll
    for (int mi = 0; mi < 2; mi++) {
        int b = warp_m * 32 + mi * 16 + (lane >> 2);
        #pragma unroll
        for (int ni = 0; ni < 4; ni++) {
            int n = n0 + warp_n * 32 + (ni >> 1) * 16 + (ni & 1) * 8 + (lane & 3) * 2;
            atomicAdd(&g_concat[b * CONC + n],           acc[mi][ni][0]);
            atomicAdd(&g_concat[b * CONC + n + 1],       acc[mi][ni][1]);
            atomicAdd(&g_concat[(b + 8) * CONC + n],     acc[mi][ni][2]);
            atomicAdd(&g_concat[(b + 8) * CONC + n + 1], acc[mi][ni][3]);
        }
    }
}

// ======================= init kernels =======================
__global__ void init_concat(const float* __restrict__ bb) {
    int i = blockIdx.x * 256 + threadIdx.x;
    if (i < BB * EMB) g_concat[(i >> 9) * CONC + (i & 511)] = bb[i & 511];
}
__global__ void init_h(const float* __restrict__ hb) {
    int i = blockIdx.x * 256 + threadIdx.x;
    if (i < BB * HID) g_h[i] = hb[i % HID];
}
__global__ void init_hid(const float* __restrict__ stb1, const float* __restrict__ ageb1,
                         const float* __restrict__ genb1) {
    int i = blockIdx.x * 256 + threadIdx.x;
    if (i < BB * 1400) {
        int c = i % 1400;
        g_hid[i] = (c < 600) ? stb1[c] : (c < 1000 ? ageb1[c - 600] : genb1[c - 1000]);
    }
}

// ============ fused histogram: one x read; row cached in SMEM ============
#define HIST_SMEM (HWP * 4 + 16 * 100 * 4 + 256)
__global__ __launch_bounds__(512) void hist_fused(const float* __restrict__ x) {
    extern __shared__ float srow[];                   // HWP floats
    int*   bins = (int*)(srow + HWP);                 // [16][100]
    float* red  = (float*)(bins + 1600);              // 34 floats
    int r = blockIdx.x;
    int t = threadIdx.x, w = t >> 5, lane = t & 31;
    const float4* rg = (const float4*)(x + (size_t)r * HWP);
    float4* sr4 = (float4*)srow;

    float mn = 1e30f, mx = -1e30f;
    for (int i = t; i < HWP / 4; i += 512) {
        float4 v = rg[i];
        sr4[i] = v;
        mn = fminf(mn, fminf(fminf(v.x, v.y), fminf(v.z, v.w)));
        mx = fmaxf(mx, fmaxf(fmaxf(v.x, v.y), fmaxf(v.z, v.w)));
    }
    for (int o = 16; o > 0; o >>= 1) {
        mn = fminf(mn, __shfl_xor_sync(0xffffffffu, mn, o));
        mx = fmaxf(mx, __shfl_xor_sync(0xffffffffu, mx, o));
    }
    if (lane == 0) { red[w] = mn; red[16 + w] = mx; }
    for (int i = t; i < 1600; i += 512) bins[i] = 0;
    __syncthreads();
    if (t == 0) {
        float a = red[0], b = red[16];
        for (int k = 1; k < 16; k++) { a = fminf(a, red[k]); b = fmaxf(b, red[16 + k]); }
        red[32] = a; red[33] = b;
    }
    __syncthreads();
    float mnv = red[32], mxv = red[33];
    float width = (mxv > mnv) ? (mxv - mnv) : 1.0f;
    int* mybins = bins + w * 100;

    for (int i = t; i < HWP / 4; i += 512) {
        float4 v = sr4[i];
        int i0 = (int)floorf((v.x - mnv) / width * 100.0f);
        int i1 = (int)floorf((v.y - mnv) / width * 100.0f);
        int i2 = (int)floorf((v.z - mnv) / width * 100.0f);
        int i3 = (int)floorf((v.w - mnv) / width * 100.0f);
        i0 = min(max(i0, 0), 99); i1 = min(max(i1, 0), 99);
        i2 = min(max(i2, 0), 99); i3 = min(max(i3, 0), 99);
        atomicAdd(&mybins[i0], 1);
        atomicAdd(&mybins[i1], 1);
        atomicAdd(&mybins[i2], 1);
        atomicAdd(&mybins[i3], 1);
    }
    __syncthreads();
    if (t < 100) {
        int s = 0;
        #pragma unroll
        for (int k = 0; k < 16; k++) s += bins[k * 100 + t];
        int b = r / 3, c = r % 3;
        g_concat[b * CONC + EMB + c * 100 + t] = (float)s;
    }
}

// ============ mid GEMM: out[b,n] += in[b,:].Wt[n,:] (fine K-split atomics) ============
__global__ __launch_bounds__(256) void mid_gemm(const float* __restrict__ in, int istride, int Kfull,
                                                const float* __restrict__ Wt,
                                                float* __restrict__ out, int ostride, int N,
                                                int relu_in) {
    __shared__ float is[64][33];
    __shared__ float ws[64][33];
    int n0 = blockIdx.x * 64;
    int k0 = blockIdx.y * 32;
    int t = threadIdx.x;
    int tn = t & 15, tb = t >> 4;
    float acc[4][4] = {};
    #pragma unroll
    for (int e = 0; e < 8; e++) {
        int idx = t + e * 256;
        int row = idx >> 5, col = idx & 31;
        float iv = (k0 + col < Kfull) ? in[(size_t)row * istride + k0 + col] : 0.f;
        if (relu_in) iv = fmaxf(iv, 0.f);
        is[row][col] = iv;
        int n = n0 + row;
        ws[row][col] = (n < N && k0 + col < Kfull) ? Wt[(size_t)n * Kfull + k0 + col] : 0.f;
    }
    __syncthreads();
    #pragma unroll
    for (int kk = 0; kk < 32; kk++) {
        float xv[4], wv[4];
        #pragma unroll
        for (int i2 = 0; i2 < 4; i2++) xv[i2] = is[tb + 16 * i2][kk];
        #pragma unroll
        for (int j = 0; j < 4; j++) wv[j] = ws[tn + 16 * j][kk];
        #pragma unroll
        for (int i2 = 0; i2 < 4; i2++)
            #pragma unroll
            for (int j = 0; j < 4; j++) acc[i2][j] += xv[i2] * wv[j];
    }
    #pragma unroll
    for (int i2 = 0; i2 < 4; i2++) {
        int b = tb + 16 * i2;
        #pragma unroll
        for (int j = 0; j < 4; j++) {
            int n = n0 + tn + 16 * j;
            if (n < N) atomicAdd(&out[(size_t)b * ostride + n], acc[i2][j]);
        }
    }
}

// ============ merged head layer-1: g_hid[b,n] += relu(g_h[b,:]).W(n)[.,:] ============
__global__ __launch_bounds__(256) void heads1_gemm(const float* __restrict__ stW1,
                                                   const float* __restrict__ ageW1,
                                                   const float* __restrict__ genW1) {
    __shared__ float is[64][33];
    __shared__ float ws[64][33];
    int n0 = blockIdx.x * 64;
    int k0 = blockIdx.y * 32;
    int t = threadIdx.x;
    int tn = t & 15, tb = t >> 4;
    #pragma unroll
    for (int e = 0; e < 8; e++) {
        int idx = t + e * 256;
        int row = idx >> 5, col = idx & 31;
        float iv = (k0 + col < HID) ? fmaxf(g_h[(size_t)row * HID + k0 + col], 0.f) : 0.f;
        is[row][col] = iv;
        int n = n0 + row;
        float wv = 0.f;
        if (n < 1400 && k0 + col < HID) {
            const float* p = (n < 600) ? (stW1 + (size_t)n * HID)
                           : (n < 1000) ? (ageW1 + (size_t)(n - 600) * HID)
                                        : (genW1 + (size_t)(n - 1000) * HID);
            wv = p[k0 + col];
        }
        ws[row][col] = wv;
    }
    __syncthreads();
    float acc[4][4] = {};
    #pragma unroll
    for (int kk = 0; kk < 32; kk++) {
        float xv[4], wv[4];
        #pragma unroll
        for (int i2 = 0; i2 < 4; i2++) xv[i2] = is[tb + 16 * i2][kk];
        #pragma unroll
        for (int j = 0; j < 4; j++) wv[j] = ws[tn + 16 * j][kk];
        #pragma unroll
        for (int i2 = 0; i2 < 4; i2++)
            #pragma unroll
            for (int j = 0; j < 4; j++) acc[i2][j] += xv[i2] * wv[j];
    }
    #pragma unroll
    for (int i2 = 0; i2 < 4; i2++) {
        int b = tb + 16 * i2;
        #pragma unroll
        for (int j = 0; j < 4; j++) {
            int n = n0 + tn + 16 * j;
            if (n < 1400) atomicAdd(&g_hid[(size_t)b * 1400 + n], acc[i2][j]);
        }
    }
}

// ================= fused heads: relu(hid) -> 16 logits + relu + 3 softmaxes =================
__global__ __launch_bounds__(256) void heads_kernel(const float* __restrict__ stW2, const float* __restrict__ stb2,
                                                    const float* __restrict__ ageW2, const float* __restrict__ ageb2,
                                                    const float* __restrict__ genW2, const float* __restrict__ genb2,
                                                    float* __restrict__ out) {
    int b = blockIdx.x;
    __shared__ float sh[1400];
    __shared__ float slog[16];
    int t = threadIdx.x;
    for (int i = t; i < 1400; i += 256) sh[i] = fmaxf(g_hid[b * 1400 + i], 0.f);
    __syncthreads();
    int w = t >> 5, lane = t & 31;
    for (int l = w; l < 16; l += 8) {
        const float* wr; const float* basep; int len; float bv;
        if (l < 10)      { wr = stW2  + l * 600;        basep = sh;        len = 600; bv = stb2[l]; }
        else if (l < 14) { wr = ageW2 + (l - 10) * 400; basep = sh + 600;  len = 400; bv = ageb2[l - 10]; }
        else             { wr = genW2 + (l - 14) * 400; basep = sh + 1000; len = 400; bv = genb2[l - 14]; }
        float s = 0.f;
        for (int i = lane; i < len; i += 32) s += basep[i] * wr[i];
        for (int o = 16; o > 0; o >>= 1) s += __shfl_xor_sync(0xffffffffu, s, o);
        if (lane == 0) slog[l] = fmaxf(s + bv, 0.f);
    }
    __syncthreads();
    if (t == 0) {
        float m = slog[0];
        for (int i = 1; i < 10; i++) m = fmaxf(m, slog[i]);
        float e[10], sum = 0.f;
        for (int i = 0; i < 10; i++) { e[i] = expf(slog[i] - m); sum += e[i]; }
        for (int i = 0; i < 10; i++) out[b * 10 + i] = e[i] / sum;
    } else if (t == 32) {
        float m = slog[10];
        for (int i = 11; i < 14; i++) m = fmaxf(m, slog[i]);
        float e[4], sum = 0.f;
        for (int i = 0; i < 4; i++) { e[i] = expf(slog[10 + i] - m); sum += e[i]; }
        for (int i = 0; i < 4; i++) out[640 + b * 4 + i] = e[i] / sum;
    } else if (t == 64) {
        float m = fmaxf(slog[14], slog[15]);
        float e0 = expf(slog[14] - m), e1 = expf(slog[15] - m);
        float inv = 1.f / (e0 + e1);
        out[896 + b * 2]     = e0 * inv;
        out[896 + b * 2 + 1] = e1 * inv;
    }
}

extern "C" void kernel_launch(void* const* d_in, const int* in_sizes, int n_in,
                              void* d_out, int out_size) {
    const float* x      = (const float*)d_in[0];
    const float* base_W = (const float*)d_in[1];
    const float* base_b = (const float*)d_in[2];
    const float* hW     = (const float*)d_in[3];
    const float* hb     = (const float*)d_in[4];
    const float* stW1   = (const float*)d_in[5];
    const float* stb1   = (const float*)d_in[6];
    const float* stW2   = (const float*)d_in[7];
    const float* stb2   = (const float*)d_in[8];
    const float* ageW1  = (const float*)d_in[9];
    const float* ageb1  = (const float*)d_in[10];
    const float* ageW2  = (const float*)d_in[11];
    const float* ageb2  = (const float*)d_in[12];
    const float* genW1  = (const float*)d_in[13];
    const float* genb1  = (const float*)d_in[14];
    const float* genW2  = (const float*)d_in[15];
    const float* genb2  = (const float*)d_in[16];
    float* out = (float*)d_out;

    float *pc = nullptr, *ph = nullptr;
    cudaGetSymbolAddress((void**)&pc, g_concat);
    cudaGetSymbolAddress((void**)&ph, g_h);

    cudaFuncSetAttribute(hist_fused, cudaFuncAttributeMaxDynamicSharedMemorySize, HIST_SMEM);

    init_concat<<<(BB * EMB + 255) / 256, 256>>>(base_b);
    init_h<<<(BB * HID + 255) / 256, 256>>>(hb);
    init_hid<<<(BB * 1400 + 255) / 256, 256>>>(stb1, ageb1, genb1);
    hist_fused<<<BB * CHN, 512, HIST_SMEM>>>(x);
    gemm1<<<dim3(4, KSPLIT), 256>>>(x, base_W);

    // h_pre = concat @ hW.T (+hb pre-initialized); K=812 -> 26 k-chunks
    mid_gemm<<<dim3(7, 26), 256>>>(pc, CONC, CONC, hW, ph, HID, HID, 0);
    // merged head layer-1: N=1400, K=400 -> 13 k-chunks
    heads1_gemm<<<dim3(22, 13), 256>>>(stW1, ageW1, genW1);

    heads_kernel<<<BB, 256>>>(stW2, stb2, ageW2, ageb2, genW2, genb2, out);
}

// round 6
// speedup vs baseline: 2.7818x; 1.1608x over previous
#include <cuda_runtime.h>
#include <cstdint>

#define BB   64
#define CHN  3
#define HWP  (224*224)
#define KBIG (CHN*HWP)
#define EMB  512
#define CONC 812
#define HID  400

__device__ float g_concat[BB*CONC];     // [64][812]: xm | hist
__device__ float g_h[BB*HID];           // [64][400] pre-activation
__device__ float g_hid[BB*1400];        // [64][600|400|400] pre-activation
__device__ unsigned g_mm[BB*CHN*2];     // per-(b,c) min/max as monotone keys

__device__ __forceinline__ uint32_t smem_u32(const void* p) {
    uint32_t a;
    asm("{ .reg .u64 t; cvta.to.shared.u64 t, %1; cvt.u32.u64 %0, t; }" : "=r"(a) : "l"(p));
    return a;
}

__device__ __forceinline__ void ldm4(uint32_t* r, uint32_t addr) {
    asm volatile("ldmatrix.sync.aligned.m8n8.x4.shared.b16 {%0,%1,%2,%3}, [%4];"
        : "=r"(r[0]), "=r"(r[1]), "=r"(r[2]), "=r"(r[3]) : "r"(addr));
}

__device__ __forceinline__ void mma16816(float* d, const uint32_t* a, const uint32_t* b) {
    asm volatile("mma.sync.aligned.m16n8k16.row.col.f32.bf16.bf16.f32 "
        "{%0,%1,%2,%3}, {%4,%5,%6,%7}, {%8,%9}, {%0,%1,%2,%3};"
        : "+f"(d[0]), "+f"(d[1]), "+f"(d[2]), "+f"(d[3])
        : "r"(a[0]), "r"(a[1]), "r"(a[2]), "r"(a[3]), "r"(b[0]), "r"(b[1]));
}

// split fp32x4 -> bf16 hi pair + bf16 lo pair (low halfword = lower k)
__device__ __forceinline__ void cvt_split(float4 v, uint32_t& h01, uint32_t& h23,
                                          uint32_t& l01, uint32_t& l23) {
    asm("cvt.rn.bf16x2.f32 %0, %1, %2;" : "=r"(h01) : "f"(v.y), "f"(v.x));
    asm("cvt.rn.bf16x2.f32 %0, %1, %2;" : "=r"(h23) : "f"(v.w), "f"(v.z));
    float r0 = v.x - __uint_as_float(h01 << 16);
    float r1 = v.y - __uint_as_float(h01 & 0xffff0000u);
    float r2 = v.z - __uint_as_float(h23 << 16);
    float r3 = v.w - __uint_as_float(h23 & 0xffff0000u);
    asm("cvt.rn.bf16x2.f32 %0, %1, %2;" : "=r"(l01) : "f"(r1), "f"(r0));
    asm("cvt.rn.bf16x2.f32 %0, %1, %2;" : "=r"(l23) : "f"(r3), "f"(r2));
}

// monotone key transform for float atomic min/max on uint
__device__ __forceinline__ unsigned fkey(float f) {
    unsigned b = __float_as_uint(f);
    return (b & 0x80000000u) ? ~b : (b | 0x80000000u);
}
__device__ __forceinline__ float funkey(unsigned k) {
    unsigned b = (k & 0x80000000u) ? (k & 0x7fffffffu) : ~k;
    return __uint_as_float(b);
}

// ===== big GEMM: concat[b,n] += x[b,:].W[n,:]  (bf16 3-term split, HMMA, pipelined) =====
#define KSPLIT 74
__global__ __launch_bounds__(256, 2) void gemm1(const float* __restrict__ x,
                                                const float* __restrict__ W) {
    __shared__ __align__(128) uint8_t smraw[49152];
    uint32_t base = smem_u32(smraw);
    const uint32_t XHI = base, XLO = base + 8192, WHI = base + 16384, WLO = base + 32768;

    int tid = threadIdx.x, wid = tid >> 5, lane = tid & 31;
    int warp_m = wid >> 2;
    int warp_n = wid & 3;
    int n0 = blockIdx.x * 128;
    int ky = blockIdx.y;
    int t0 = ky * 31 + (ky < 58 ? ky : 58);
    int cnt = 31 + (ky < 58 ? 1 : 0);

    int ar = lane & 7, ag = lane >> 3;
    int a_row_off = (ag & 1) * 8 + ar;
    int a_col_off = (ag >> 1) * 16;
    int b_row_off = (ag >> 1) * 8 + ar;
    int b_col_off = (ag & 1) * 16;

    float acc[2][4][4];
    #pragma unroll
    for (int i = 0; i < 2; i++)
        #pragma unroll
        for (int j = 0; j < 4; j++)
            #pragma unroll
            for (int q = 0; q < 4; q++) acc[i][j][q] = 0.f;

    int lrow = tid >> 4, lc4 = tid & 15;
    const float* xp = x + (size_t)lrow * KBIG + lc4 * 4;
    const float* wp = W + (size_t)(n0 + lrow) * KBIG + lc4 * 4;

    float4 xv[4], wv[8];
    // prologue: load tile 0
    {
        size_t k0 = (size_t)t0 * 64;
        #pragma unroll
        for (int e = 0; e < 4; e++) xv[e] = *(const float4*)(xp + (size_t)(e * 16) * KBIG + k0);
        #pragma unroll
        for (int e = 0; e < 8; e++) wv[e] = *(const float4*)(wp + (size_t)(e * 16) * KBIG + k0);
    }

    for (int it = 0; it < cnt; ++it) {
        __syncthreads();   // previous tile's mma reads done; smem free
        {
            uint32_t off0 = (uint32_t)(lrow * 128 + ((lc4 * 8) ^ ((lrow & 7) << 4)));
            #pragma unroll
            for (int e = 0; e < 4; e++) {
                uint32_t off = off0 + e * 2048;
                uint32_t h01, h23, l01, l23;
                cvt_split(xv[e], h01, h23, l01, l23);
                asm volatile("st.shared.v2.b32 [%0], {%1, %2};" :: "r"(XHI + off), "r"(h01), "r"(h23));
                asm volatile("st.shared.v2.b32 [%0], {%1, %2};" :: "r"(XLO + off), "r"(l01), "r"(l23));
            }
            #pragma unroll
            for (int e = 0; e < 8; e++) {
                uint32_t off = off0 + e * 2048;
                uint32_t h01, h23, l01, l23;
                cvt_split(wv[e], h01, h23, l01, l23);
                asm volatile("st.shared.v2.b32 [%0], {%1, %2};" :: "r"(WHI + off), "r"(h01), "r"(h23));
                asm volatile("st.shared.v2.b32 [%0], {%1, %2};" :: "r"(WLO + off), "r"(l01), "r"(l23));
            }
        }
        __syncthreads();
        if (it + 1 < cnt) {   // prefetch next tile; latency hidden behind mma phase
            size_t k0 = (size_t)(t0 + it + 1) * 64;
            #pragma unroll
            for (int e = 0; e < 4; e++) xv[e] = *(const float4*)(xp + (size_t)(e * 16) * KBIG + k0);
            #pragma unroll
            for (int e = 0; e < 8; e++) wv[e] = *(const float4*)(wp + (size_t)(e * 16) * KBIG + k0);
        }
        #pragma unroll
        for (int ks = 0; ks < 4; ++ks) {
            int cbase = ks * 32;
            uint32_t ah[2][4], al[2][4], bh[2][4], bl[2][4];
            #pragma unroll
            for (int mi = 0; mi < 2; mi++) {
                int r = warp_m * 32 + mi * 16 + a_row_off;
                uint32_t col = (uint32_t)(cbase + a_col_off) ^ ((r & 7) << 4);
                ldm4(ah[mi], XHI + r * 128 + col);
                ldm4(al[mi], XLO + r * 128 + col);
            }
            #pragma unroll
            for (int ni = 0; ni < 2; ni++) {
                int r = warp_n * 32 + ni * 16 + b_row_off;
                uint32_t col = (uint32_t)(cbase + b_col_off) ^ ((r & 7) << 4);
                ldm4(bh[ni], WHI + r * 128 + col);
                ldm4(bl[ni], WLO + r * 128 + col);
            }
            #pragma unroll
            for (int mi = 0; mi < 2; mi++)
                #pragma unroll
                for (int ni = 0; ni < 2; ni++)
                    #pragma unroll
                    for (int nj = 0; nj < 2; nj++) {
                        float* d = acc[mi][ni * 2 + nj];
                        mma16816(d, ah[mi], bh[ni] + nj * 2);
                        mma16816(d, ah[mi], bl[ni] + nj * 2);
                        mma16816(d, al[mi], bh[ni] + nj * 2);
                    }
        }
    }

    #pragma unroll
    for (int mi = 0; mi < 2; mi++) {
        int b = warp_m * 32 + mi * 16 + (lane >> 2);
        #pragma unroll
        for (int ni = 0; ni < 4; ni++) {
            int n = n0 + warp_n * 32 + (ni >> 1) * 16 + (ni & 1) * 8 + (lane & 3) * 2;
            atomicAdd(&g_concat[b * CONC + n],           acc[mi][ni][0]);
            atomicAdd(&g_concat[b * CONC + n + 1],       acc[mi][ni][1]);
            atomicAdd(&g_concat[(b + 8) * CONC + n],     acc[mi][ni][2]);
            atomicAdd(&g_concat[(b + 8) * CONC + n + 1], acc[mi][ni][3]);
        }
    }
}

// ======================= merged init =======================
// [0,32768): concat xm bias; [.,+25600): g_h bias; [.,+89600): g_hid bias;
// [.,+19200): concat hist = 0; [.,+384): g_mm keys
#define INIT_TOTAL (32768 + 25600 + 89600 + 19200 + 384)
__global__ void init_all(const float* __restrict__ bb, const float* __restrict__ hb,
                         const float* __restrict__ stb1, const float* __restrict__ ageb1,
                         const float* __restrict__ genb1) {
    int i = blockIdx.x * 256 + threadIdx.x;
    if (i < 32768) { g_concat[(i >> 9) * CONC + (i & 511)] = bb[i & 511]; return; }
    i -= 32768;
    if (i < 25600) { g_h[i] = hb[i % HID]; return; }
    i -= 25600;
    if (i < 89600) {
        int c = i % 1400;
        g_hid[i] = (c < 600) ? stb1[c] : (c < 1000 ? ageb1[c - 600] : genb1[c - 1000]);
        return;
    }
    i -= 89600;
    if (i < 19200) {
        int b = i / 300, c = i % 300;
        g_concat[b * CONC + EMB + c] = 0.f;
        return;
    }
    i -= 19200;
    if (i < 384) g_mm[i] = (i & 1) ? 0u : 0xFFFFFFFFu;   // even=min-key, odd=max-key
}

// ============ hist pass 1: min/max, 4 CTAs per (b,c) row ============
#define SEG (HWP / 4)          // 12544 elems per CTA
__global__ __launch_bounds__(256) void hist_minmax(const float* __restrict__ x) {
    int r = blockIdx.x >> 2, seg = blockIdx.x & 3;
    const float4* rg = (const float4*)(x + (size_t)r * HWP + (size_t)seg * SEG);
    __shared__ unsigned s_red[16];
    int t = threadIdx.x, w = t >> 5, lane = t & 31;
    float mn = 1e30f, mx = -1e30f;
    for (int i = t; i < SEG / 4; i += 256) {
        float4 v = rg[i];
        mn = fminf(mn, fminf(fminf(v.x, v.y), fminf(v.z, v.w)));
        mx = fmaxf(mx, fmaxf(fmaxf(v.x, v.y), fmaxf(v.z, v.w)));
    }
    for (int o = 16; o > 0; o >>= 1) {
        mn = fminf(mn, __shfl_xor_sync(0xffffffffu, mn, o));
        mx = fmaxf(mx, __shfl_xor_sync(0xffffffffu, mx, o));
    }
    if (lane == 0) { s_red[w] = fkey(mn); s_red[8 + w] = fkey(mx); }
    __syncthreads();
    if (t == 0) {
        unsigned a = s_red[0], b = s_red[8];
        for (int k = 1; k < 8; k++) { a = min(a, s_red[k]); b = max(b, s_red[8 + k]); }
        atomicMin(&g_mm[r * 2], a);
        atomicMax(&g_mm[r * 2 + 1], b);
    }
}

// ============ hist pass 2: binning, 4 CTAs per row ============
__global__ __launch_bounds__(256) void hist_bins(const float* __restrict__ x) {
    int r = blockIdx.x >> 2, seg = blockIdx.x & 3;
    const float4* rg = (const float4*)(x + (size_t)r * HWP + (size_t)seg * SEG);
    __shared__ int s_bins[8][100];
    int t = threadIdx.x, w = t >> 5;
    for (int i = t; i < 800; i += 256) s_bins[0][i] = 0;
    __syncthreads();
    float mnv = funkey(g_mm[r * 2]);
    float mxv = funkey(g_mm[r * 2 + 1]);
    float width = (mxv > mnv) ? (mxv - mnv) : 1.0f;
    for (int i = t; i < SEG / 4; i += 256) {
        float4 v = rg[i];
        int i0 = (int)floorf((v.x - mnv) / width * 100.0f);
        int i1 = (int)floorf((v.y - mnv) / width * 100.0f);
        int i2 = (int)floorf((v.z - mnv) / width * 100.0f);
        int i3 = (int)floorf((v.w - mnv) / width * 100.0f);
        i0 = min(max(i0, 0), 99); i1 = min(max(i1, 0), 99);
        i2 = min(max(i2, 0), 99); i3 = min(max(i3, 0), 99);
        atomicAdd(&s_bins[w][i0], 1);
        atomicAdd(&s_bins[w][i1], 1);
        atomicAdd(&s_bins[w][i2], 1);
        atomicAdd(&s_bins[w][i3], 1);
    }
    __syncthreads();
    if (t < 100) {
        int s = 0;
        #pragma unroll
        for (int k = 0; k < 8; k++) s += s_bins[k][t];
        int b = r / 3, c = r % 3;
        atomicAdd(&g_concat[b * CONC + EMB + c * 100 + t], (float)s);
    }
}

// ============ mid GEMM: out[b,n] += in[b,:].Wt[n,:] (fine K-split atomics) ============
__global__ __launch_bounds__(256) void mid_gemm(const float* __restrict__ in, int istride, int Kfull,
                                                const float* __restrict__ Wt,
                                                float* __restrict__ out, int ostride, int N,
                                                int relu_in) {
    __shared__ float is[64][33];
    __shared__ float ws[64][33];
    int n0 = blockIdx.x * 64;
    int k0 = blockIdx.y * 32;
    int t = threadIdx.x;
    int tn = t & 15, tb = t >> 4;
    float acc[4][4] = {};
    #pragma unroll
    for (int e = 0; e < 8; e++) {
        int idx = t + e * 256;
        int row = idx >> 5, col = idx & 31;
        float iv = (k0 + col < Kfull) ? in[(size_t)row * istride + k0 + col] : 0.f;
        if (relu_in) iv = fmaxf(iv, 0.f);
        is[row][col] = iv;
        int n = n0 + row;
        ws[row][col] = (n < N && k0 + col < Kfull) ? Wt[(size_t)n * Kfull + k0 + col] : 0.f;
    }
    __syncthreads();
    #pragma unroll
    for (int kk = 0; kk < 32; kk++) {
        float xv[4], wv[4];
        #pragma unroll
        for (int i2 = 0; i2 < 4; i2++) xv[i2] = is[tb + 16 * i2][kk];
        #pragma unroll
        for (int j = 0; j < 4; j++) wv[j] = ws[tn + 16 * j][kk];
        #pragma unroll
        for (int i2 = 0; i2 < 4; i2++)
            #pragma unroll
            for (int j = 0; j < 4; j++) acc[i2][j] += xv[i2] * wv[j];
    }
    #pragma unroll
    for (int i2 = 0; i2 < 4; i2++) {
        int b = tb + 16 * i2;
        #pragma unroll
        for (int j = 0; j < 4; j++) {
            int n = n0 + tn + 16 * j;
            if (n < N) atomicAdd(&out[(size_t)b * ostride + n], acc[i2][j]);
        }
    }
}

// ============ merged head layer-1: g_hid[b,n] += relu(g_h[b,:]).W(n)[.,:] ============
__global__ __launch_bounds__(256) void heads1_gemm(const float* __restrict__ stW1,
                                                   const float* __restrict__ ageW1,
                                                   const float* __restrict__ genW1) {
    __shared__ float is[64][33];
    __shared__ float ws[64][33];
    int n0 = blockIdx.x * 64;
    int k0 = blockIdx.y * 32;
    int t = threadIdx.x;
    int tn = t & 15, tb = t >> 4;
    #pragma unroll
    for (int e = 0; e < 8; e++) {
        int idx = t + e * 256;
        int row = idx >> 5, col = idx & 31;
        float iv = (k0 + col < HID) ? fmaxf(g_h[(size_t)row * HID + k0 + col], 0.f) : 0.f;
        is[row][col] = iv;
        int n = n0 + row;
        float wv = 0.f;
        if (n < 1400 && k0 + col < HID) {
            const float* p = (n < 600) ? (stW1 + (size_t)n * HID)
                           : (n < 1000) ? (ageW1 + (size_t)(n - 600) * HID)
                                        : (genW1 + (size_t)(n - 1000) * HID);
            wv = p[k0 + col];
        }
        ws[row][col] = wv;
    }
    __syncthreads();
    float acc[4][4] = {};
    #pragma unroll
    for (int kk = 0; kk < 32; kk++) {
        float xv[4], wv[4];
        #pragma unroll
        for (int i2 = 0; i2 < 4; i2++) xv[i2] = is[tb + 16 * i2][kk];
        #pragma unroll
        for (int j = 0; j < 4; j++) wv[j] = ws[tn + 16 * j][kk];
        #pragma unroll
        for (int i2 = 0; i2 < 4; i2++)
            #pragma unroll
            for (int j = 0; j < 4; j++) acc[i2][j] += xv[i2] * wv[j];
    }
    #pragma unroll
    for (int i2 = 0; i2 < 4; i2++) {
        int b = tb + 16 * i2;
        #pragma unroll
        for (int j = 0; j < 4; j++) {
            int n = n0 + tn + 16 * j;
            if (n < 1400) atomicAdd(&g_hid[(size_t)b * 1400 + n], acc[i2][j]);
        }
    }
}

// ================= fused heads: relu(hid) -> 16 logits + relu + 3 softmaxes =================
__global__ __launch_bounds__(256) void heads_kernel(const float* __restrict__ stW2, const float* __restrict__ stb2,
                                                    const float* __restrict__ ageW2, const float* __restrict__ ageb2,
                                                    const float* __restrict__ genW2, const float* __restrict__ genb2,
                                                    float* __restrict__ out) {
    int b = blockIdx.x;
    __shared__ float sh[1400];
    __shared__ float slog[16];
    int t = threadIdx.x;
    for (int i = t; i < 1400; i += 256) sh[i] = fmaxf(g_hid[b * 1400 + i], 0.f);
    __syncthreads();
    int w = t >> 5, lane = t & 31;
    for (int l = w; l < 16; l += 8) {
        const float* wr; const float* basep; int len; float bv;
        if (l < 10)      { wr = stW2  + l * 600;        basep = sh;        len = 600; bv = stb2[l]; }
        else if (l < 14) { wr = ageW2 + (l - 10) * 400; basep = sh + 600;  len = 400; bv = ageb2[l - 10]; }
        else             { wr = genW2 + (l - 14) * 400; basep = sh + 1000; len = 400; bv = genb2[l - 14]; }
        float s = 0.f;
        for (int i = lane; i < len; i += 32) s += basep[i] * wr[i];
        for (int o = 16; o > 0; o >>= 1) s += __shfl_xor_sync(0xffffffffu, s, o);
        if (lane == 0) slog[l] = fmaxf(s + bv, 0.f);
    }
    __syncthreads();
    if (t == 0) {
        float m = slog[0];
        for (int i = 1; i < 10; i++) m = fmaxf(m, slog[i]);
        float e[10], sum = 0.f;
        for (int i = 0; i < 10; i++) { e[i] = expf(slog[i] - m); sum += e[i]; }
        for (int i = 0; i < 10; i++) out[b * 10 + i] = e[i] / sum;
    } else if (t == 32) {
        float m = slog[10];
        for (int i = 11; i < 14; i++) m = fmaxf(m, slog[i]);
        float e[4], sum = 0.f;
        for (int i = 0; i < 4; i++) { e[i] = expf(slog[10 + i] - m); sum += e[i]; }
        for (int i = 0; i < 4; i++) out[640 + b * 4 + i] = e[i] / sum;
    } else if (t == 64) {
        float m = fmaxf(slog[14], slog[15]);
        float e0 = expf(slog[14] - m), e1 = expf(slog[15] - m);
        float inv = 1.f / (e0 + e1);
        out[896 + b * 2]     = e0 * inv;
        out[896 + b * 2 + 1] = e1 * inv;
    }
}

extern "C" void kernel_launch(void* const* d_in, const int* in_sizes, int n_in,
                              void* d_out, int out_size) {
    const float* x      = (const float*)d_in[0];
    const float* base_W = (const float*)d_in[1];
    const float* base_b = (const float*)d_in[2];
    const float* hW     = (const float*)d_in[3];
    const float* hb     = (const float*)d_in[4];
    const float* stW1   = (const float*)d_in[5];
    const float* stb1   = (const float*)d_in[6];
    const float* stW2   = (const float*)d_in[7];
    const float* stb2   = (const float*)d_in[8];
    const float* ageW1  = (const float*)d_in[9];
    const float* ageb1  = (const float*)d_in[10];
    const float* ageW2  = (const float*)d_in[11];
    const float* ageb2  = (const float*)d_in[12];
    const float* genW1  = (const float*)d_in[13];
    const float* genb1  = (const float*)d_in[14];
    const float* genW2  = (const float*)d_in[15];
    const float* genb2  = (const float*)d_in[16];
    float* out = (float*)d_out;

    float *pc = nullptr, *ph = nullptr;
    cudaGetSymbolAddress((void**)&pc, g_concat);
    cudaGetSymbolAddress((void**)&ph, g_h);

    init_all<<<(INIT_TOTAL + 255) / 256, 256>>>(base_b, hb, stb1, ageb1, genb1);
    hist_minmax<<<BB * CHN * 4, 256>>>(x);
    hist_bins<<<BB * CHN * 4, 256>>>(x);
    gemm1<<<dim3(4, KSPLIT), 256>>>(x, base_W);

    mid_gemm<<<dim3(7, 26), 256>>>(pc, CONC, CONC, hW, ph, HID, HID, 0);
    heads1_gemm<<<dim3(22, 13), 256>>>(stW1, ageW1, genW1);
    heads_kernel<<<BB, 256>>>(stW2, stb2, ageW2, ageb2, genW2, genb2, out);
}